// round 9
// baseline (speedup 1.0000x reference)
#include <cuda_runtime.h>

#define IN_CH 128
#define HID 64
#define OUT 32
#define MAXN 100000
#define MAXE 1600000
#define SCAN_B 512
#define NBMAX ((MAXN + SCAN_B - 1) / SCAN_B)

__device__ int   g_idx[2 * MAXE];       // [0,E)=src, [E,2E)=dst
__device__ int   g_csr[MAXE];           // src ids grouped by dst
__device__ int   g_cnt[MAXN];
__device__ int   g_fill[MAXN];
__device__ int   g_off[MAXN + 1];
__device__ int   g_bsum[NBMAX];
__device__ float g_dinv[MAXN];
__device__ float g_h1[MAXN * HID];      // x @ W1 (unscaled)
__device__ float g_agg1[MAXN * HID];
__device__ float g_h2[MAXN * OUT];      // (relu(agg1) @ W2) * dinv
__device__ int   g_is64;

// ---- 1. dtype probe: edge_index may be int64 or int32 ----
__global__ void probe_kernel(const unsigned long long* __restrict__ ei) {
    if (threadIdx.x == 0 && blockIdx.x == 0) {
        int is64 = 1;
#pragma unroll
        for (int j = 0; j < 8; j++)
            if (ei[j] >> 32) is64 = 0;
        g_is64 = is64;
    }
}

// ---- 2. zero counters ----
__global__ void zero_kernel(int n) {
    int i = blockIdx.x * blockDim.x + threadIdx.x;
    if (i < n) { g_cnt[i] = 0; g_fill[i] = 0; }
}

// ---- 3. fused convert + dst histogram ----
__global__ void convhist_kernel(const void* __restrict__ ei, int E) {
    int i = blockIdx.x * blockDim.x + threadIdx.x;
    if (i >= 2 * E) return;
    int v;
    if (g_is64) v = (int)((const long long*)ei)[i];
    else        v = ((const int*)ei)[i];
    g_idx[i] = v;
    if (i >= E) atomicAdd(&g_cnt[v], 1);
}

// ---- 4. GEMM1: h1 = x @ W1 (N x 128 @ 128 x 64) ----
// 256 nodes/block, 256 threads; thread = (slot 0..63) x (cb 0..3)*16
// 4 nodes x 16 channels per thread, k in chunks of 16.
#define TILE_N1 256
#define KC1 16
__global__ __launch_bounds__(256) void gemm1_kernel(const float* __restrict__ x,
                                                    const float* __restrict__ W, int n) {
    __shared__ float xs[TILE_N1][KC1 + 1];   // stride 17 -> conflict-free
    __shared__ float Ws[KC1 * HID];          // 16 x 64
    int t = threadIdx.x;
    int block0 = blockIdx.x * TILE_N1;
    int slot = t >> 2;
    int cb = (t & 3) * 16;
    int nbase = block0 + slot * 4;

    float acc[4][16];
#pragma unroll
    for (int u = 0; u < 4; u++)
#pragma unroll
        for (int j = 0; j < 16; j++) acc[u][j] = 0.0f;

    for (int kc = 0; kc < IN_CH; kc += KC1) {
        // stage x chunk: thread t loads node block0+t, 16 floats
        {
            int node = block0 + t;
            if (node < n) {
                const float4* src = (const float4*)(x + (size_t)node * IN_CH + kc);
#pragma unroll
                for (int q = 0; q < 4; q++) {
                    float4 v = src[q];
                    xs[t][q * 4 + 0] = v.x;
                    xs[t][q * 4 + 1] = v.y;
                    xs[t][q * 4 + 2] = v.z;
                    xs[t][q * 4 + 3] = v.w;
                }
            } else {
#pragma unroll
                for (int q = 0; q < 16; q++) xs[t][q] = 0.0f;
            }
        }
        // stage W chunk: 1024 contiguous floats, 1 float4 per thread
        ((float4*)Ws)[t] = ((const float4*)(W + kc * HID))[t];
        __syncthreads();

#pragma unroll
        for (int kk = 0; kk < KC1; kk++) {
            float w[16];
#pragma unroll
            for (int j = 0; j < 16; j++) w[j] = Ws[kk * HID + cb + j];
#pragma unroll
            for (int u = 0; u < 4; u++) {
                float xv = xs[slot * 4 + u][kk];
#pragma unroll
                for (int j = 0; j < 16; j++) acc[u][j] = fmaf(xv, w[j], acc[u][j]);
            }
        }
        __syncthreads();
    }

#pragma unroll
    for (int u = 0; u < 4; u++) {
        int node = nbase + u;
        if (node < n) {
            float4* o = (float4*)(g_h1 + (size_t)node * HID + cb);
#pragma unroll
            for (int q = 0; q < 4; q++)
                o[q] = make_float4(acc[u][q * 4], acc[u][q * 4 + 1],
                                   acc[u][q * 4 + 2], acc[u][q * 4 + 3]);
        }
    }
}

// ---- 5. scan phase 1 ----
__global__ void scan1(int n) {
    __shared__ int s[SCAN_B];
    int tid = threadIdx.x;
    int i = blockIdx.x * SCAN_B + tid;
    int v = (i < n) ? g_cnt[i] : 0;
    s[tid] = v;
    __syncthreads();
#pragma unroll
    for (int off = 1; off < SCAN_B; off <<= 1) {
        int t = (tid >= off) ? s[tid - off] : 0;
        __syncthreads();
        s[tid] += t;
        __syncthreads();
    }
    if (i < n) g_off[i] = s[tid] - v;
    if (tid == SCAN_B - 1) g_bsum[blockIdx.x] = s[tid];
}

// ---- 6. scan phase 2 (parallel, nb <= SCAN_B) ----
__global__ void scan2(int nb) {
    __shared__ int s[SCAN_B];
    int tid = threadIdx.x;
    int v = (tid < nb) ? g_bsum[tid] : 0;
    s[tid] = v;
    __syncthreads();
#pragma unroll
    for (int off = 1; off < SCAN_B; off <<= 1) {
        int t = (tid >= off) ? s[tid - off] : 0;
        __syncthreads();
        s[tid] += t;
        __syncthreads();
    }
    if (tid < nb) g_bsum[tid] = s[tid] - v;
}

// ---- 7. scan phase 3 + dinv ----
__global__ void scan3(int n, int E) {
    int i = blockIdx.x * blockDim.x + threadIdx.x;
    if (i < n) {
        g_off[i] += g_bsum[i / SCAN_B];
        g_dinv[i] = rsqrtf((float)(g_cnt[i] + 1));
    }
    if (i == 0) g_off[n] = E;
}

// ---- 8. fill CSR ----
__global__ void fill_kernel(int E) {
    int e = blockIdx.x * blockDim.x + threadIdx.x;
    if (e >= E) return;
    int src = g_idx[e];
    int dst = g_idx[E + e];
    int pos = g_off[dst] + atomicAdd(&g_fill[dst], 1);
    g_csr[pos] = src;
}

// ---- 9. agg1: warp/node, lane = float2 pair ----
__global__ void agg1_kernel(const float* __restrict__ b1, int n) {
    int warp = (blockIdx.x * blockDim.x + threadIdx.x) >> 5;
    int lane = threadIdx.x & 31;
    if (warp >= n) return;
    int beg = g_off[warp];
    int end = g_off[warp + 1];
    float dd = g_dinv[warp];

    const float2* h = (const float2*)g_h1;
    float2 self = h[(size_t)warp * 32 + lane];
    float2 acc = make_float2(self.x * dd, self.y * dd);

    int j = beg;
    for (; j + 8 <= end; j += 8) {
        int s[8];
        float w[8];
#pragma unroll
        for (int u = 0; u < 8; u++) s[u] = g_csr[j + u];
#pragma unroll
        for (int u = 0; u < 8; u++) w[u] = g_dinv[s[u]];
#pragma unroll
        for (int u = 0; u < 8; u++) {
            float2 hv = h[(size_t)s[u] * 32 + lane];
            acc.x = fmaf(hv.x, w[u], acc.x);
            acc.y = fmaf(hv.y, w[u], acc.y);
        }
    }
    for (; j < end; j++) {
        int s = g_csr[j];
        float w = g_dinv[s];
        float2 hv = h[(size_t)s * 32 + lane];
        acc.x = fmaf(hv.x, w, acc.x);
        acc.y = fmaf(hv.y, w, acc.y);
    }
    float2 b = ((const float2*)b1)[lane];
    acc.x = fmaf(acc.x, dd, b.x);
    acc.y = fmaf(acc.y, dd, b.y);
    ((float2*)g_agg1)[(size_t)warp * 32 + lane] = acc;
}

// ---- 10. GEMM2: h2s = (relu(agg1) @ W2) * dinv ----
// 256 nodes/block, 256 threads; thread = (slot 0..127) x (cb 0..1)*16
// 2 nodes x 16 channels per thread, k in chunks of 32.
#define TILE_N2 256
#define KC2 32
__global__ __launch_bounds__(256) void gemm2_kernel(const float* __restrict__ W, int n) {
    __shared__ float xs[TILE_N2][KC2 + 1];   // stride 33 -> conflict-free
    __shared__ float Ws[KC2 * OUT];          // 32 x 32
    int t = threadIdx.x;
    int block0 = blockIdx.x * TILE_N2;
    int slot = t >> 1;
    int cb = (t & 1) * 16;
    int nbase = block0 + slot * 2;

    float acc[2][16];
#pragma unroll
    for (int u = 0; u < 2; u++)
#pragma unroll
        for (int j = 0; j < 16; j++) acc[u][j] = 0.0f;

    for (int kc = 0; kc < HID; kc += KC2) {
        // stage relu(agg1) chunk: thread t loads node block0+t, 32 floats
        {
            int node = block0 + t;
            if (node < n) {
                const float4* src = (const float4*)(g_agg1 + (size_t)node * HID + kc);
#pragma unroll
                for (int q = 0; q < 8; q++) {
                    float4 v = src[q];
                    xs[t][q * 4 + 0] = fmaxf(v.x, 0.0f);
                    xs[t][q * 4 + 1] = fmaxf(v.y, 0.0f);
                    xs[t][q * 4 + 2] = fmaxf(v.z, 0.0f);
                    xs[t][q * 4 + 3] = fmaxf(v.w, 0.0f);
                }
            } else {
#pragma unroll
                for (int q = 0; q < 32; q++) xs[t][q] = 0.0f;
            }
        }
        // stage W2 chunk: 32x32 = 1024 contiguous floats, 1 float4 per thread
        ((float4*)Ws)[t] = ((const float4*)(W + kc * OUT))[t];
        __syncthreads();

#pragma unroll
        for (int kk = 0; kk < KC2; kk++) {
            float w[16];
#pragma unroll
            for (int j = 0; j < 16; j++) w[j] = Ws[kk * OUT + cb + j];
#pragma unroll
            for (int u = 0; u < 2; u++) {
                float xv = xs[slot * 2 + u][kk];
#pragma unroll
                for (int j = 0; j < 16; j++) acc[u][j] = fmaf(xv, w[j], acc[u][j]);
            }
        }
        __syncthreads();
    }

#pragma unroll
    for (int u = 0; u < 2; u++) {
        int node = nbase + u;
        if (node < n) {
            float d = g_dinv[node];
            float4* o = (float4*)(g_h2 + (size_t)node * OUT + cb);
#pragma unroll
            for (int q = 0; q < 4; q++)
                o[q] = make_float4(acc[u][q * 4] * d, acc[u][q * 4 + 1] * d,
                                   acc[u][q * 4 + 2] * d, acc[u][q * 4 + 3] * d);
        }
    }
}

// ---- 11. agg2: warp/node, lane = channel ----
__global__ void agg2_kernel(const float* __restrict__ b2, float* __restrict__ out, int n) {
    int warp = (blockIdx.x * blockDim.x + threadIdx.x) >> 5;
    int lane = threadIdx.x & 31;
    if (warp >= n) return;
    int beg = g_off[warp];
    int end = g_off[warp + 1];

    float acc = g_h2[(size_t)warp * 32 + lane];    // self-loop

    int j = beg;
    for (; j + 8 <= end; j += 8) {
        int s[8];
#pragma unroll
        for (int u = 0; u < 8; u++) s[u] = g_csr[j + u];
        float hv[8];
#pragma unroll
        for (int u = 0; u < 8; u++) hv[u] = g_h2[(size_t)s[u] * 32 + lane];
#pragma unroll
        for (int u = 0; u < 8; u++) acc += hv[u];
    }
    for (; j < end; j++)
        acc += g_h2[(size_t)g_csr[j] * 32 + lane];

    out[(size_t)warp * 32 + lane] = fmaf(acc, g_dinv[warp], b2[lane]);
}

// ---------------- launch ----------------
extern "C" void kernel_launch(void* const* d_in, const int* in_sizes, int n_in,
                              void* d_out, int out_size) {
    const float* x  = (const float*)d_in[0];
    const void*  ei = d_in[1];
    const float* W1 = (const float*)d_in[2];
    const float* b1 = (const float*)d_in[3];
    const float* W2 = (const float*)d_in[4];
    const float* b2 = (const float*)d_in[5];
    float* out = (float*)d_out;

    int N = in_sizes[0] / IN_CH;
    int E = in_sizes[1] / 2;
    const int B = 256;
    int nb = (N + SCAN_B - 1) / SCAN_B;

    probe_kernel<<<1, 32>>>((const unsigned long long*)ei);              // 1
    zero_kernel<<<(N + B - 1) / B, B>>>(N);                              // 2
    convhist_kernel<<<(2 * E + B - 1) / B, B>>>(ei, E);                  // 3
    gemm1_kernel<<<(N + TILE_N1 - 1) / TILE_N1, 256>>>(x, W1, N);        // 4  <- profiled slot
    scan1<<<nb, SCAN_B>>>(N);                                            // 5
    scan2<<<1, SCAN_B>>>(nb);                                            // 6
    scan3<<<(N + B - 1) / B, B>>>(N, E);                                 // 7
    fill_kernel<<<(E + B - 1) / B, B>>>(E);                              // 8
    agg1_kernel<<<(N * 32 + B - 1) / B, B>>>(b1, N);                     // 9
    gemm2_kernel<<<(N + TILE_N2 - 1) / TILE_N2, 256>>>(W2, N);           // 10
    agg2_kernel<<<(N * 32 + B - 1) / B, B>>>(b2, out, N);                // 11
}

// round 10
// speedup vs baseline: 1.0060x; 1.0060x over previous
#include <cuda_runtime.h>

#define IN_CH 128
#define HID 64
#define OUT 32
#define MAXN 100000
#define MAXE 1600000
#define SCAN_B 512
#define NBMAX ((MAXN + SCAN_B - 1) / SCAN_B)

__device__ int   g_idx[2 * MAXE];       // [0,E)=src, [E,2E)=dst
__device__ int   g_csr[MAXE];           // src ids grouped by dst
__device__ int   g_cnt[MAXN];
__device__ int   g_fill[MAXN];
__device__ int   g_off[MAXN + 1];
__device__ int   g_bsum[NBMAX];
__device__ float g_dinv[MAXN];
__device__ float g_h1[MAXN * HID];      // x @ W1 (unscaled)
__device__ float g_agg1[MAXN * HID];
__device__ float g_h2[MAXN * OUT];      // (relu(agg1) @ W2) * dinv
__device__ int   g_is64;

// ---- 1. dtype probe: edge_index may be int64 or int32 ----
__global__ void probe_kernel(const unsigned long long* __restrict__ ei) {
    if (threadIdx.x == 0 && blockIdx.x == 0) {
        int is64 = 1;
#pragma unroll
        for (int j = 0; j < 8; j++)
            if (ei[j] >> 32) is64 = 0;
        g_is64 = is64;
    }
}

// ---- 2. zero counters ----
__global__ void zero_kernel(int n) {
    int i = blockIdx.x * blockDim.x + threadIdx.x;
    if (i < n) { g_cnt[i] = 0; g_fill[i] = 0; }
}

// ---- 3. fused convert + dst histogram ----
__global__ void convhist_kernel(const void* __restrict__ ei, int E) {
    int i = blockIdx.x * blockDim.x + threadIdx.x;
    if (i >= 2 * E) return;
    int v;
    if (g_is64) v = (int)((const long long*)ei)[i];
    else        v = ((const int*)ei)[i];
    g_idx[i] = v;
    if (i >= E) atomicAdd(&g_cnt[v], 1);
}

// ---- 4. GEMM1: h1 = x @ W1 (N x 128 @ 128 x 64) ----
// 256 nodes/block, 256 threads; thread = (slot 0..63) x (cb 0..3)*16
// 4 nodes x 16 channels per thread, k in chunks of 16.
#define TILE_N1 256
#define KC1 16
__global__ __launch_bounds__(256) void gemm1_kernel(const float* __restrict__ x,
                                                    const float* __restrict__ W, int n) {
    __shared__ float xs[TILE_N1][KC1 + 1];   // stride 17 -> conflict-free
    __shared__ float Ws[KC1 * HID];          // 16 x 64
    int t = threadIdx.x;
    int block0 = blockIdx.x * TILE_N1;
    int slot = t >> 2;
    int cb = (t & 3) * 16;
    int nbase = block0 + slot * 4;

    float acc[4][16];
#pragma unroll
    for (int u = 0; u < 4; u++)
#pragma unroll
        for (int j = 0; j < 16; j++) acc[u][j] = 0.0f;

    for (int kc = 0; kc < IN_CH; kc += KC1) {
        // stage x chunk: thread t loads node block0+t, 16 floats
        {
            int node = block0 + t;
            if (node < n) {
                const float4* src = (const float4*)(x + (size_t)node * IN_CH + kc);
#pragma unroll
                for (int q = 0; q < 4; q++) {
                    float4 v = src[q];
                    xs[t][q * 4 + 0] = v.x;
                    xs[t][q * 4 + 1] = v.y;
                    xs[t][q * 4 + 2] = v.z;
                    xs[t][q * 4 + 3] = v.w;
                }
            } else {
#pragma unroll
                for (int q = 0; q < 16; q++) xs[t][q] = 0.0f;
            }
        }
        // stage W chunk: 1024 contiguous floats, 1 float4 per thread
        ((float4*)Ws)[t] = ((const float4*)(W + kc * HID))[t];
        __syncthreads();

#pragma unroll
        for (int kk = 0; kk < KC1; kk++) {
            float w[16];
#pragma unroll
            for (int j = 0; j < 16; j++) w[j] = Ws[kk * HID + cb + j];
#pragma unroll
            for (int u = 0; u < 4; u++) {
                float xv = xs[slot * 4 + u][kk];
#pragma unroll
                for (int j = 0; j < 16; j++) acc[u][j] = fmaf(xv, w[j], acc[u][j]);
            }
        }
        __syncthreads();
    }

#pragma unroll
    for (int u = 0; u < 4; u++) {
        int node = nbase + u;
        if (node < n) {
            float4* o = (float4*)(g_h1 + (size_t)node * HID + cb);
#pragma unroll
            for (int q = 0; q < 4; q++)
                o[q] = make_float4(acc[u][q * 4], acc[u][q * 4 + 1],
                                   acc[u][q * 4 + 2], acc[u][q * 4 + 3]);
        }
    }
}

// ---- 5. scan phase 1 ----
__global__ void scan1(int n) {
    __shared__ int s[SCAN_B];
    int tid = threadIdx.x;
    int i = blockIdx.x * SCAN_B + tid;
    int v = (i < n) ? g_cnt[i] : 0;
    s[tid] = v;
    __syncthreads();
#pragma unroll
    for (int off = 1; off < SCAN_B; off <<= 1) {
        int t = (tid >= off) ? s[tid - off] : 0;
        __syncthreads();
        s[tid] += t;
        __syncthreads();
    }
    if (i < n) g_off[i] = s[tid] - v;
    if (tid == SCAN_B - 1) g_bsum[blockIdx.x] = s[tid];
}

// ---- 6. scan phase 2 (parallel, nb <= SCAN_B) ----
__global__ void scan2(int nb) {
    __shared__ int s[SCAN_B];
    int tid = threadIdx.x;
    int v = (tid < nb) ? g_bsum[tid] : 0;
    s[tid] = v;
    __syncthreads();
#pragma unroll
    for (int off = 1; off < SCAN_B; off <<= 1) {
        int t = (tid >= off) ? s[tid - off] : 0;
        __syncthreads();
        s[tid] += t;
        __syncthreads();
    }
    if (tid < nb) g_bsum[tid] = s[tid] - v;
}

// ---- 7. scan phase 3 + dinv ----
__global__ void scan3(int n, int E) {
    int i = blockIdx.x * blockDim.x + threadIdx.x;
    if (i < n) {
        g_off[i] += g_bsum[i / SCAN_B];
        g_dinv[i] = rsqrtf((float)(g_cnt[i] + 1));
    }
    if (i == 0) g_off[n] = E;
}

// ---- 8. fill CSR ----
__global__ void fill_kernel(int E) {
    int e = blockIdx.x * blockDim.x + threadIdx.x;
    if (e >= E) return;
    int src = g_idx[e];
    int dst = g_idx[E + e];
    int pos = g_off[dst] + atomicAdd(&g_fill[dst], 1);
    g_csr[pos] = src;
}

// ---- 9. agg1: warp/node, lane = float2 pair ----
__global__ void agg1_kernel(const float* __restrict__ b1, int n) {
    int warp = (blockIdx.x * blockDim.x + threadIdx.x) >> 5;
    int lane = threadIdx.x & 31;
    if (warp >= n) return;
    int beg = g_off[warp];
    int end = g_off[warp + 1];
    float dd = g_dinv[warp];

    const float2* h = (const float2*)g_h1;
    float2 self = h[(size_t)warp * 32 + lane];
    float2 acc = make_float2(self.x * dd, self.y * dd);

    int j = beg;
    for (; j + 8 <= end; j += 8) {
        int s[8];
        float w[8];
#pragma unroll
        for (int u = 0; u < 8; u++) s[u] = g_csr[j + u];
#pragma unroll
        for (int u = 0; u < 8; u++) w[u] = g_dinv[s[u]];
#pragma unroll
        for (int u = 0; u < 8; u++) {
            float2 hv = h[(size_t)s[u] * 32 + lane];
            acc.x = fmaf(hv.x, w[u], acc.x);
            acc.y = fmaf(hv.y, w[u], acc.y);
        }
    }
    for (; j < end; j++) {
        int s = g_csr[j];
        float w = g_dinv[s];
        float2 hv = h[(size_t)s * 32 + lane];
        acc.x = fmaf(hv.x, w, acc.x);
        acc.y = fmaf(hv.y, w, acc.y);
    }
    float2 b = ((const float2*)b1)[lane];
    acc.x = fmaf(acc.x, dd, b.x);
    acc.y = fmaf(acc.y, dd, b.y);
    ((float2*)g_agg1)[(size_t)warp * 32 + lane] = acc;
}

// ---- 10. GEMM2: h2s = (relu(agg1) @ W2) * dinv ----
// 256 nodes/block, 256 threads; thread = (slot 0..127) x (cb 0..1)*16
// 2 nodes x 16 channels per thread, k in chunks of 32.
#define TILE_N2 256
#define KC2 32
__global__ __launch_bounds__(256) void gemm2_kernel(const float* __restrict__ W, int n) {
    __shared__ float xs[TILE_N2][KC2 + 1];   // stride 33 -> conflict-free
    __shared__ float Ws[KC2 * OUT];          // 32 x 32
    int t = threadIdx.x;
    int block0 = blockIdx.x * TILE_N2;
    int slot = t >> 1;
    int cb = (t & 1) * 16;
    int nbase = block0 + slot * 2;

    float acc[2][16];
#pragma unroll
    for (int u = 0; u < 2; u++)
#pragma unroll
        for (int j = 0; j < 16; j++) acc[u][j] = 0.0f;

    for (int kc = 0; kc < HID; kc += KC2) {
        // stage relu(agg1) chunk: thread t loads node block0+t, 32 floats
        {
            int node = block0 + t;
            if (node < n) {
                const float4* src = (const float4*)(g_agg1 + (size_t)node * HID + kc);
#pragma unroll
                for (int q = 0; q < 8; q++) {
                    float4 v = src[q];
                    xs[t][q * 4 + 0] = fmaxf(v.x, 0.0f);
                    xs[t][q * 4 + 1] = fmaxf(v.y, 0.0f);
                    xs[t][q * 4 + 2] = fmaxf(v.z, 0.0f);
                    xs[t][q * 4 + 3] = fmaxf(v.w, 0.0f);
                }
            } else {
#pragma unroll
                for (int q = 0; q < 32; q++) xs[t][q] = 0.0f;
            }
        }
        // stage W2 chunk: 32x32 = 1024 contiguous floats, 1 float4 per thread
        ((float4*)Ws)[t] = ((const float4*)(W + kc * OUT))[t];
        __syncthreads();

#pragma unroll
        for (int kk = 0; kk < KC2; kk++) {
            float w[16];
#pragma unroll
            for (int j = 0; j < 16; j++) w[j] = Ws[kk * OUT + cb + j];
#pragma unroll
            for (int u = 0; u < 2; u++) {
                float xv = xs[slot * 2 + u][kk];
#pragma unroll
                for (int j = 0; j < 16; j++) acc[u][j] = fmaf(xv, w[j], acc[u][j]);
            }
        }
        __syncthreads();
    }

#pragma unroll
    for (int u = 0; u < 2; u++) {
        int node = nbase + u;
        if (node < n) {
            float d = g_dinv[node];
            float4* o = (float4*)(g_h2 + (size_t)node * OUT + cb);
#pragma unroll
            for (int q = 0; q < 4; q++)
                o[q] = make_float4(acc[u][q * 4] * d, acc[u][q * 4 + 1] * d,
                                   acc[u][q * 4 + 2] * d, acc[u][q * 4 + 3] * d);
        }
    }
}

// ---- 11. agg2: warp/node, lane = channel ----
__global__ void agg2_kernel(const float* __restrict__ b2, float* __restrict__ out, int n) {
    int warp = (blockIdx.x * blockDim.x + threadIdx.x) >> 5;
    int lane = threadIdx.x & 31;
    if (warp >= n) return;
    int beg = g_off[warp];
    int end = g_off[warp + 1];

    float acc = g_h2[(size_t)warp * 32 + lane];    // self-loop

    int j = beg;
    for (; j + 8 <= end; j += 8) {
        int s[8];
#pragma unroll
        for (int u = 0; u < 8; u++) s[u] = g_csr[j + u];
        float hv[8];
#pragma unroll
        for (int u = 0; u < 8; u++) hv[u] = g_h2[(size_t)s[u] * 32 + lane];
#pragma unroll
        for (int u = 0; u < 8; u++) acc += hv[u];
    }
    for (; j < end; j++)
        acc += g_h2[(size_t)g_csr[j] * 32 + lane];

    out[(size_t)warp * 32 + lane] = fmaf(acc, g_dinv[warp], b2[lane]);
}

// ---------------- launch ----------------
extern "C" void kernel_launch(void* const* d_in, const int* in_sizes, int n_in,
                              void* d_out, int out_size) {
    const float* x  = (const float*)d_in[0];
    const void*  ei = d_in[1];
    const float* W1 = (const float*)d_in[2];
    const float* b1 = (const float*)d_in[3];
    const float* W2 = (const float*)d_in[4];
    const float* b2 = (const float*)d_in[5];
    float* out = (float*)d_out;

    int N = in_sizes[0] / IN_CH;
    int E = in_sizes[1] / 2;
    const int B = 256;
    int nb = (N + SCAN_B - 1) / SCAN_B;

    probe_kernel<<<1, 32>>>((const unsigned long long*)ei);              // 1
    zero_kernel<<<(N + B - 1) / B, B>>>(N);                              // 2
    convhist_kernel<<<(2 * E + B - 1) / B, B>>>(ei, E);                  // 3
    gemm1_kernel<<<(N + TILE_N1 - 1) / TILE_N1, 256>>>(x, W1, N);        // 4  <- profiled slot
    scan1<<<nb, SCAN_B>>>(N);                                            // 5
    scan2<<<1, SCAN_B>>>(nb);                                            // 6
    scan3<<<(N + B - 1) / B, B>>>(N, E);                                 // 7
    fill_kernel<<<(E + B - 1) / B, B>>>(E);                              // 8
    agg1_kernel<<<(N * 32 + B - 1) / B, B>>>(b1, N);                     // 9
    gemm2_kernel<<<(N + TILE_N2 - 1) / TILE_N2, 256>>>(W2, N);           // 10
    agg2_kernel<<<(N * 32 + B - 1) / B, B>>>(b2, out, N);                // 11
}